// round 1
// baseline (speedup 1.0000x reference)
#include <cuda_runtime.h>
#include <cstddef>

#define NB     2
#define N_IN   163842
#define N_OUT  40962
#define CDIM   128
#define KCAND  7

// Scratch: weighted-sum pool and weight denominator (static device globals —
// no allocation at runtime, per harness rules).
__device__ float g_down[(size_t)NB * N_OUT * CDIM];
__device__ float g_denom[N_OUT];

// ---------------------------------------------------------------------------
// Kernel 0: zero the scratch (must re-zero every launch: graph-replayed).
// ---------------------------------------------------------------------------
__global__ void zero_kernel() {
    const size_t total4 = (size_t)NB * N_OUT * CDIM / 4;  // float4 count
    size_t i = (size_t)blockIdx.x * blockDim.x + threadIdx.x;
    if (i < total4) {
        reinterpret_cast<float4*>(g_down)[i] = make_float4(0.f, 0.f, 0.f, 0.f);
    }
    if (i < N_OUT) {
        g_denom[i] = 0.f;
    }
}

// ---------------------------------------------------------------------------
// Kernel 1: scatter-add  down[b, parent[n], :] += omega[n] * x[b, n, :]
//           denom[parent[n]] += omega[n]
// One warp per input row n; lane covers 4 channels (32*4 = 128 = C).
// Vector reduction red.global.add.v4.f32 (sm_90+) => 1 instr per 16 bytes.
// ---------------------------------------------------------------------------
__global__ void scatter_kernel(const float* __restrict__ x,
                               const float* __restrict__ omega,
                               const int*   __restrict__ parent) {
    const int warp = (int)(((size_t)blockIdx.x * blockDim.x + threadIdx.x) >> 5);
    const int lane = threadIdx.x & 31;
    if (warp >= N_IN) return;

    const int   p  = parent[warp];   // broadcast load
    const float om = omega[warp];    // broadcast load

#pragma unroll
    for (int b = 0; b < NB; ++b) {
        const float4* xrow =
            reinterpret_cast<const float4*>(x + ((size_t)b * N_IN + warp) * CDIM);
        float4 v = xrow[lane];
        v.x *= om; v.y *= om; v.z *= om; v.w *= om;
        float* dst = g_down + ((size_t)b * N_OUT + p) * CDIM + lane * 4;
        asm volatile("red.global.add.v4.f32 [%0], {%1, %2, %3, %4};"
                     :: "l"(dst), "f"(v.x), "f"(v.y), "f"(v.z), "f"(v.w)
                     : "memory");
    }
    if (lane == 0) {
        atomicAdd(&g_denom[p], om);
    }
}

// ---------------------------------------------------------------------------
// Kernel 2: per input row n:
//   w[k]   = exp(-delta^2 / (2*sigma^2)) * mask ; normalized over K
//   out[b,n,:] = sum_k (w[k] / max(denom[cand[k]],1e-8)) * down[b, cand[k], :]
// One warp per n; lane covers 4 channels; loop over b reusing weights/indices.
// down (42 MB) is L2-resident, so the 7x gather is an L2-bandwidth op.
// ---------------------------------------------------------------------------
__global__ void gather_kernel(const float* __restrict__ delta,
                              const float* __restrict__ mask,
                              const int*   __restrict__ cand,
                              float*       __restrict__ out) {
    const int warp = (int)(((size_t)blockIdx.x * blockDim.x + threadIdx.x) >> 5);
    const int lane = threadIdx.x & 31;
    if (warp >= N_IN) return;

    // 1 / (2 * 0.4^2) = 3.125
    const float INV2S2 = 3.125f;

    float wk[KCAND];
    int   idx[KCAND];
    float wsum = 0.f;
#pragma unroll
    for (int k = 0; k < KCAND; ++k) {
        const size_t o = (size_t)warp * KCAND + k;
        float d = delta[o];          // broadcast within warp
        float m = mask[o];
        idx[k]  = cand[o];
        wk[k]   = __expf(-d * d * INV2S2) * m;
        wsum   += wk[k];
    }
    const float inv_wsum = 1.f / fmaxf(wsum, 1e-8f);
#pragma unroll
    for (int k = 0; k < KCAND; ++k) {
        const float den = fmaxf(g_denom[idx[k]], 1e-8f);
        wk[k] = wk[k] * inv_wsum / den;
    }

#pragma unroll
    for (int b = 0; b < NB; ++b) {
        float4 acc = make_float4(0.f, 0.f, 0.f, 0.f);
#pragma unroll
        for (int k = 0; k < KCAND; ++k) {
            const float4* row = reinterpret_cast<const float4*>(
                g_down + ((size_t)b * N_OUT + idx[k]) * CDIM);
            const float4 v = __ldg(&row[lane]);
            acc.x = fmaf(wk[k], v.x, acc.x);
            acc.y = fmaf(wk[k], v.y, acc.y);
            acc.z = fmaf(wk[k], v.z, acc.z);
            acc.w = fmaf(wk[k], v.w, acc.w);
        }
        reinterpret_cast<float4*>(out + ((size_t)b * N_IN + warp) * CDIM)[lane] = acc;
    }
}

// ---------------------------------------------------------------------------
// Launcher. Input order (metadata): x, omega, delta, cand_mask, parent_idx,
// cand_idx. Output: float32 (B, N_IN, C).
// ---------------------------------------------------------------------------
extern "C" void kernel_launch(void* const* d_in, const int* in_sizes, int n_in,
                              void* d_out, int out_size) {
    const float* x      = (const float*)d_in[0];
    const float* omega  = (const float*)d_in[1];
    const float* delta  = (const float*)d_in[2];
    const float* mask   = (const float*)d_in[3];
    const int*   parent = (const int*)d_in[4];
    const int*   cand   = (const int*)d_in[5];
    float*       out    = (float*)d_out;

    (void)in_sizes; (void)n_in; (void)out_size;

    // Zero scratch
    {
        const size_t total4 = (size_t)NB * N_OUT * CDIM / 4;
        const int threads = 256;
        const int blocks  = (int)((total4 + threads - 1) / threads);
        zero_kernel<<<blocks, threads>>>();
    }
    // Scatter pool
    {
        const int threads = 256;                 // 8 warps / block
        const int warps   = N_IN;
        const int blocks  = (warps + 8 - 1) / 8;
        scatter_kernel<<<blocks, threads>>>(x, omega, parent);
    }
    // Gather + weight
    {
        const int threads = 256;
        const int warps   = N_IN;
        const int blocks  = (warps + 8 - 1) / 8;
        gather_kernel<<<blocks, threads>>>(delta, mask, cand, out);
    }
}